// round 9
// baseline (speedup 1.0000x reference)
#include <cuda_runtime.h>
#include <cstdint>

#define BB 128
#define TT 4096
#define KK 64
#define CHUNK 64
#define NCH   (TT / CHUNK)   /* 64 chunks */
#define GRP   8              /* chunks walked per backward group (32 KB) */
#define NTHR  256

// scratch (static __device__: allocation-free)
__device__ __align__(16) uint8_t g_bp[(size_t)BB * TT * KK];   // 32 MB backpointers
__device__ int g_lasttag[BB];

__device__ __forceinline__ void cpasync16(uint32_t saddr, const void* gptr) {
    asm volatile("cp.async.ca.shared.global [%0], [%1], 16;" :: "r"(saddr), "l"(gptr));
}
__device__ __forceinline__ void cpasync_commit() {
    asm volatile("cp.async.commit_group;");
}
__device__ __forceinline__ void cpasync_wait1() {
    asm volatile("cp.async.wait_group 1;");
}

// packed f32x2 helpers (Blackwell)
__device__ __forceinline__ unsigned long long addx2(unsigned long long a, unsigned long long b) {
    unsigned long long d;
    asm("add.rn.f32x2 %0, %1, %2;" : "=l"(d) : "l"(a), "l"(b));
    return d;
}
__device__ __forceinline__ unsigned long long fma2(unsigned long long a, unsigned long long b,
                                                   unsigned long long c) {
    unsigned long long d;
    asm("fma.rn.f32x2 %0, %1, %2, %3;" : "=l"(d) : "l"(a), "l"(b), "l"(c));
    return d;
}
__device__ __forceinline__ float lo32(unsigned long long x) { return __uint_as_float((unsigned)x); }
__device__ __forceinline__ float hi32(unsigned long long x) { return __uint_as_float((unsigned)(x >> 32)); }
__device__ __forceinline__ unsigned ulo(unsigned long long x) { return (unsigned)x; }
__device__ __forceinline__ unsigned uhi(unsigned long long x) { return (unsigned)(x >> 32); }

#define NEG1X2 0xBF800000BF800000ULL   /* (-1.0f, -1.0f) */

// =====================================================================
// Forward Viterbi, 256 threads = 64 k-columns x 4 predecessor quarters.
// Thread (k, jg) reduces over j in [16*jg, 16*jg+16).
// Integer-key argmax: d_i = vmax - v_i (>=+0; +0 iff max), key = bits(d)*2+i,
// min key -> first-index argmax (exact, matches jnp.argmax).
// =====================================================================
__global__ __launch_bounds__(NTHR) void fwd_kernel(const float* __restrict__ pot,
                                                   const float* __restrict__ trans) {
    const int b   = blockIdx.x;
    const int tid = threadIdx.x;
    const int k   = tid >> 2;   // 0..63
    const int jg  = tid & 3;    // 0..3

    __shared__ __align__(16) float   st_s[2][KK];
    __shared__ __align__(16) float   ebuf[2][CHUNK * KK];   // 32 KB emission dbuf
    __shared__ __align__(16) uint8_t bps[CHUNK][KK];        // 4 KB bp staging

    // packed transition pairs: trp[i] = (T[jg*16+2i][k], T[jg*16+2i+1][k])
    unsigned long long trp[8];
#pragma unroll
    for (int i = 0; i < 8; ++i) {
        unsigned a = __float_as_uint(trans[(jg * 16 + 2 * i) * KK + k]);
        unsigned c = __float_as_uint(trans[(jg * 16 + 2 * i + 1) * KK + k]);
        trp[i] = (unsigned long long)a | ((unsigned long long)c << 32);
    }

    const float* pb  = pot + (size_t)b * TT * KK;
    uint8_t*     bpb = g_bp + (size_t)b * TT * KK;

    // prologue: prefetch emission chunks 0, 1 (16 KB each)
    {
        uint32_t s0 = (uint32_t)__cvta_generic_to_shared(ebuf[0]);
        uint32_t s1 = (uint32_t)__cvta_generic_to_shared(ebuf[1]);
#pragma unroll
        for (int i = 0; i < 4; ++i)
            cpasync16(s0 + (i * NTHR + tid) * 16, pb + (i * NTHR + tid) * 4);
        cpasync_commit();
#pragma unroll
        for (int i = 0; i < 4; ++i)
            cpasync16(s1 + (i * NTHR + tid) * 16, pb + CHUNK * KK + (i * NTHR + tid) * 4);
        cpasync_commit();
        cpasync_wait1();
    }
    __syncthreads();

    if (jg == 0) {
        st_s[0][k] = ebuf[0][k];   // alpha_0
        bps[0][k]  = (uint8_t)k;   // row-0 placeholder (never applied)
    }
    __syncthreads();

    for (int c = 0; c < NCH; ++c) {
        const float* eb = ebuf[c & 1];
        const int r0 = (c == 0) ? 1 : 0;

        for (int r = r0; r < CHUNK; ++r) {
            const int t = c * CHUNK + r;
            const float* s = st_s[(t - 1) & 1] + jg * 16;
            float emit = eb[r * KK + k];          // early independent LDS

            // v = state + transitions (packed, fma pipe): 16 floats = 8 pairs
            unsigned long long vp[8];
#pragma unroll
            for (int i = 0; i < 4; ++i) {
                ulonglong2 sv = ((const ulonglong2*)s)[i];   // LDS.128
                vp[2 * i]     = addx2(sv.x, trp[2 * i]);
                vp[2 * i + 1] = addx2(sv.y, trp[2 * i + 1]);
            }

            // vmax via FMNMX tree (alu pipe)
            float mx[8];
#pragma unroll
            for (int i = 0; i < 8; ++i) mx[i] = fmaxf(lo32(vp[i]), hi32(vp[i]));
#pragma unroll
            for (int i = 0; i < 4; ++i) mx[i] = fmaxf(mx[2 * i], mx[2 * i + 1]);
            const float vmax = fmaxf(fmaxf(mx[0], mx[1]), fmaxf(mx[2], mx[3]));

            // keys: d = vmax - v (packed fma), key = bits(d)*2 + local idx
            unsigned long long vmaxp;
            asm("mov.b64 %0, {%1, %1};" : "=l"(vmaxp) : "r"(__float_as_uint(vmax)));
            unsigned key[16];
#pragma unroll
            for (int i = 0; i < 8; ++i) {
                unsigned long long dp = fma2(vp[i], NEG1X2, vmaxp);
                key[2 * i]     = ulo(dp) * 2u + (unsigned)(2 * i);
                key[2 * i + 1] = uhi(dp) * 2u + (unsigned)(2 * i + 1);
            }
#pragma unroll
            for (int i = 0; i < 8; ++i) key[i] = umin(key[2 * i], key[2 * i + 1]);
#pragma unroll
            for (int i = 0; i < 4; ++i) key[i] = umin(key[2 * i], key[2 * i + 1]);
            const unsigned kmin = umin(umin(key[0], key[1]), umin(key[2], key[3]));

            float best = vmax;
            int   gj   = jg * 16 + (int)kmin;   // kmin <= 15 (winner has d==+0)

            // 2-level butterfly merge across the 4 quarters (lanes tid^1, tid^2)
#pragma unroll
            for (int off = 1; off <= 2; off <<= 1) {
                float po = __shfl_xor_sync(0xffffffffu, best, off);
                int   jo = __shfl_xor_sync(0xffffffffu, gj,   off);
                bool take = (po > best) || ((po == best) && (jo < gj));
                best = fmaxf(best, po);
                gj   = take ? jo : gj;
            }

            if (jg == 0) {
                st_s[t & 1][k] = best + emit;
                bps[r][k]      = (uint8_t)gj;
            }
            __syncthreads();
        }

        // chunk boundary: flush bp chunk, prefetch chunk c+2, sync chunk c+1
        {
            uint4*       dst = (uint4*)(bpb + (size_t)c * CHUNK * KK);
            const uint4* src = (const uint4*)bps;
            dst[tid] = src[tid];          // 256 x 16B = 4 KB
        }
        if (c + 1 < NCH) {
            if (c + 2 < NCH) {
                // chunk c+2 shares parity with chunk c -> reuse its buffer
                float* enb = ebuf[c & 1];
                uint32_t sn = (uint32_t)__cvta_generic_to_shared(enb);
                const float* gsrc = pb + (size_t)(c + 2) * CHUNK * KK;
#pragma unroll
                for (int i = 0; i < 4; ++i)
                    cpasync16(sn + (i * NTHR + tid) * 16, gsrc + (i * NTHR + tid) * 4);
            }
            cpasync_commit();
            cpasync_wait1();   // chunk c+1 resident
        }
        __syncthreads();
    }

    if (tid == 0) {
        const float* fin = st_s[(TT - 1) & 1];
        float bv = fin[0]; int bk = 0;
#pragma unroll
        for (int kk = 1; kk < KK; ++kk) {
            float vv = fin[kk];
            if (vv > bv) { bv = vv; bk = kk; }
        }
        g_lasttag[b] = bk;
    }
}

// =====================================================================
// Backward: serial walk per batch through shared reloads + lengths.
// =====================================================================
__global__ __launch_bounds__(128) void bwd_kernel(const int* __restrict__ mask,
                                                  float* __restrict__ out) {
    const int b   = blockIdx.x;
    const int tid = threadIdx.x;

    __shared__ __align__(16) uint8_t wb[GRP][CHUNK][KK];   // 32 KB
    __shared__ __align__(16) float   tagseg[GRP * CHUNK];
    __shared__ int scur;

    if (tid == 0) scur = g_lasttag[b];

    const uint8_t* bpb = g_bp + (size_t)b * TT * KK;
    for (int base = NCH - GRP; base >= 0; base -= GRP) {
        const uint4* src = (const uint4*)(bpb + (size_t)base * CHUNK * KK);
        uint4* dst = (uint4*)wb;
#pragma unroll
        for (int i = 0; i < (GRP * CHUNK * KK / 16) / 128; ++i)
            dst[tid + 128 * i] = src[tid + 128 * i];
        __syncthreads();

        if (tid == 0) {
            int cur = scur;                 // tag at t = 64*(base+GRP) - 1
            for (int g = GRP - 1; g >= 0; --g) {
                tagseg[g * CHUNK + CHUNK - 1] = (float)cur;
                for (int r = CHUNK - 1; r >= 1; --r) {
                    cur = wb[g][r][cur];
                    tagseg[g * CHUNK + r - 1] = (float)cur;
                }
                cur = wb[g][0][cur];        // cross chunk boundary
            }
            scur = cur;
        }
        __syncthreads();

        float* ob = out + (size_t)b * TT + base * CHUNK;
#pragma unroll
        for (int i = 0; i < (GRP * CHUNK) / 128; ++i)
            ob[tid + 128 * i] = tagseg[tid + 128 * i];
        __syncthreads();
    }

    // sequence length
    {
        int s = 0;
        const int4* m = (const int4*)(mask + (size_t)b * TT);
        for (int i = tid; i < TT / 4; i += 128) {
            int4 v = m[i];
            s += v.x + v.y + v.z + v.w;
        }
#pragma unroll
        for (int off = 16; off; off >>= 1) s += __shfl_xor_sync(0xffffffffu, s, off);
        __shared__ int red[4];
        if ((tid & 31) == 0) red[tid >> 5] = s;
        __syncthreads();
        if (tid == 0)
            out[(size_t)BB * TT + b] = (float)(red[0] + red[1] + red[2] + red[3]);
    }
}

// =====================================================================
extern "C" void kernel_launch(void* const* d_in, const int* in_sizes, int n_in,
                              void* d_out, int out_size) {
    const float* pot   = nullptr;
    const float* trans = nullptr;
    const int*   mask  = nullptr;
    for (int i = 0; i < n_in; ++i) {
        if      (in_sizes[i] == BB * TT * KK) pot   = (const float*)d_in[i];
        else if (in_sizes[i] == KK * KK)      trans = (const float*)d_in[i];
        else if (in_sizes[i] == BB * TT)      mask  = (const int*)  d_in[i];
    }
    float* out = (float*)d_out;   // [tags (128*4096) | lengths (128)] as f32

    fwd_kernel<<<BB, NTHR>>>(pot, trans);
    bwd_kernel<<<BB, 128>>>(mask, out);
}

// round 10
// speedup vs baseline: 1.1364x; 1.1364x over previous
#include <cuda_runtime.h>
#include <cstdint>

#define BB 128
#define TT 4096
#define KK 64
#define CHUNK 64
#define NCH   (TT / CHUNK)   /* 64 chunks */
#define GRP   8              /* chunks walked per backward group (32 KB) */

// scratch (static __device__: allocation-free)
__device__ __align__(16) uint8_t g_bp[(size_t)BB * TT * KK];   // 32 MB backpointers
__device__ int g_lasttag[BB];

__device__ __forceinline__ void cpasync16(uint32_t saddr, const void* gptr) {
    asm volatile("cp.async.ca.shared.global [%0], [%1], 16;" :: "r"(saddr), "l"(gptr));
}
__device__ __forceinline__ void cpasync_commit() {
    asm volatile("cp.async.commit_group;");
}
__device__ __forceinline__ void cpasync_wait1() {
    asm volatile("cp.async.wait_group 1;");
}

// packed f32x2 helpers (Blackwell)
__device__ __forceinline__ unsigned long long addx2(unsigned long long a, unsigned long long b) {
    unsigned long long d;
    asm("add.rn.f32x2 %0, %1, %2;" : "=l"(d) : "l"(a), "l"(b));
    return d;
}
__device__ __forceinline__ unsigned long long fma2(unsigned long long a, unsigned long long b,
                                                   unsigned long long c) {
    unsigned long long d;
    asm("fma.rn.f32x2 %0, %1, %2, %3;" : "=l"(d) : "l"(a), "l"(b), "l"(c));
    return d;
}
__device__ __forceinline__ float lo32(unsigned long long x) { return __uint_as_float((unsigned)x); }
__device__ __forceinline__ float hi32(unsigned long long x) { return __uint_as_float((unsigned)(x >> 32)); }
__device__ __forceinline__ unsigned ulo(unsigned long long x) { return (unsigned)x; }
__device__ __forceinline__ unsigned uhi(unsigned long long x) { return (unsigned)(x >> 32); }

#define NEG1X2 0xBF800000BF800000ULL   /* (-1.0f, -1.0f) */

// =====================================================================
// Forward Viterbi, 128 threads = 64 k-columns x 2 predecessor halves.
// VALUE path (critical): LDS -> addx2 -> FMNMX tree -> shuffle -> +emit
// -> STS -> BAR.   INDEX path (keys, bps store) is issued AFTER the
// barrier: BAR.SYNC.DEFER_BLOCKING lets it fill the barrier-wait window;
// the deferred block fires at the next step's LDS of st_s.
// Integer-key argmax: d = vmax - v (>= +0; +0 iff max), key = bits(d)*2+i,
// min key -> first-index argmax (exact, matches jnp.argmax).
// =====================================================================
__global__ __launch_bounds__(128) void fwd_kernel(const float* __restrict__ pot,
                                                  const float* __restrict__ trans) {
    const int b   = blockIdx.x;
    const int tid = threadIdx.x;
    const int k   = tid >> 1;   // 0..63
    const int jh  = tid & 1;    // 0..1

    __shared__ __align__(16) float   st_s[2][KK];
    __shared__ __align__(16) float   ebuf[2][CHUNK * KK];   // 32 KB emission dbuf
    __shared__ __align__(16) uint8_t bps[CHUNK][KK];        // 4 KB bp staging

    // packed transition pairs: trp[i] = (T[jh*32+2i][k], T[jh*32+2i+1][k])
    unsigned long long trp[16];
#pragma unroll
    for (int i = 0; i < 16; ++i) {
        unsigned a = __float_as_uint(trans[(jh * 32 + 2 * i) * KK + k]);
        unsigned c = __float_as_uint(trans[(jh * 32 + 2 * i + 1) * KK + k]);
        trp[i] = (unsigned long long)a | ((unsigned long long)c << 32);
    }

    const float* pb  = pot + (size_t)b * TT * KK;
    uint8_t*     bpb = g_bp + (size_t)b * TT * KK;

    // prologue: prefetch emission chunks 0, 1
    {
        uint32_t s0 = (uint32_t)__cvta_generic_to_shared(ebuf[0]);
        uint32_t s1 = (uint32_t)__cvta_generic_to_shared(ebuf[1]);
#pragma unroll
        for (int i = 0; i < 8; ++i)
            cpasync16(s0 + (i * 128 + tid) * 16, pb + (i * 128 + tid) * 4);
        cpasync_commit();
#pragma unroll
        for (int i = 0; i < 8; ++i)
            cpasync16(s1 + (i * 128 + tid) * 16, pb + CHUNK * KK + (i * 128 + tid) * 4);
        cpasync_commit();
        cpasync_wait1();
    }
    __syncthreads();

    if (jh == 0) {
        st_s[0][k] = ebuf[0][k];   // alpha_0
        bps[0][k]  = (uint8_t)k;   // row-0 placeholder (never applied)
    }
    __syncthreads();

    for (int c = 0; c < NCH; ++c) {
        const float* eb = ebuf[c & 1];
        const int r0 = (c == 0) ? 1 : 0;

        for (int r = r0; r < CHUNK; ++r) {
            const int t = c * CHUNK + r;
            const float* s = st_s[(t - 1) & 1] + jh * 32;
            float emit = eb[r * KK + k];

            // ---- VALUE path (critical chain) ----
            unsigned long long vp[16];
#pragma unroll
            for (int i = 0; i < 8; ++i) {
                ulonglong2 sv = ((const ulonglong2*)s)[i];   // LDS.128
                vp[2 * i]     = addx2(sv.x, trp[2 * i]);
                vp[2 * i + 1] = addx2(sv.y, trp[2 * i + 1]);
            }
            float mx[16];
#pragma unroll
            for (int i = 0; i < 16; ++i) mx[i] = fmaxf(lo32(vp[i]), hi32(vp[i]));
#pragma unroll
            for (int i = 0; i < 8; ++i)  mx[i] = fmaxf(mx[2 * i], mx[2 * i + 1]);
#pragma unroll
            for (int i = 0; i < 4; ++i)  mx[i] = fmaxf(mx[2 * i], mx[2 * i + 1]);
            const float vmax = fmaxf(fmaxf(mx[0], mx[1]), fmaxf(mx[2], mx[3]));

            const float po   = __shfl_xor_sync(0xffffffffu, vmax, 1);
            const float best = fmaxf(vmax, po);

            if (jh == 0) st_s[t & 1][k] = best + emit;
            __syncthreads();   // DEFER_BLOCKING: index path below fills the window

            // ---- INDEX path (off critical chain; consumed at chunk flush) ----
            unsigned long long vmaxp;
            asm("mov.b64 %0, {%1, %1};" : "=l"(vmaxp) : "r"(__float_as_uint(vmax)));
            unsigned key[32];
#pragma unroll
            for (int i = 0; i < 16; ++i) {
                unsigned long long dp = fma2(vp[i], NEG1X2, vmaxp);
                key[2 * i]     = ulo(dp) * 2u + (unsigned)(2 * i);
                key[2 * i + 1] = uhi(dp) * 2u + (unsigned)(2 * i + 1);
            }
#pragma unroll
            for (int i = 0; i < 16; ++i) key[i] = umin(key[2 * i], key[2 * i + 1]);
#pragma unroll
            for (int i = 0; i < 8; ++i)  key[i] = umin(key[2 * i], key[2 * i + 1]);
#pragma unroll
            for (int i = 0; i < 4; ++i)  key[i] = umin(key[2 * i], key[2 * i + 1]);
            const unsigned kmin = umin(umin(key[0], key[1]), umin(key[2], key[3]));

            int gj = jh * 32 + (int)kmin;   // kmin <= 31 (winner has d==+0)
            int jo = __shfl_xor_sync(0xffffffffu, gj, 1);
            // first-index tie rule: jh0 holds smaller indices
            bool take = jh ? (po >= vmax) : (po > vmax);
            gj = take ? jo : gj;

            if (jh == 0) bps[r][k] = (uint8_t)gj;
        }
        __syncthreads();   // bps stores (issued post-bar) complete before flush

        // chunk boundary: flush bp chunk, prefetch chunk c+2, sync chunk c+1
        {
            uint4*       dst = (uint4*)(bpb + (size_t)c * CHUNK * KK);
            const uint4* src = (const uint4*)bps;
            dst[tid]       = src[tid];
            dst[tid + 128] = src[tid + 128];
        }
        if (c + 1 < NCH) {
            if (c + 2 < NCH) {
                // chunk c+2 shares parity with chunk c -> reuse its buffer
                float* enb = ebuf[c & 1];
                uint32_t sn = (uint32_t)__cvta_generic_to_shared(enb);
                const float* gsrc = pb + (size_t)(c + 2) * CHUNK * KK;
#pragma unroll
                for (int i = 0; i < 8; ++i)
                    cpasync16(sn + (i * 128 + tid) * 16, gsrc + (i * 128 + tid) * 4);
            }
            cpasync_commit();
            cpasync_wait1();   // chunk c+1 resident
        }
        __syncthreads();
    }

    if (tid == 0) {
        const float* fin = st_s[(TT - 1) & 1];
        float bv = fin[0]; int bk = 0;
#pragma unroll
        for (int kk = 1; kk < KK; ++kk) {
            float vv = fin[kk];
            if (vv > bv) { bv = vv; bk = kk; }
        }
        g_lasttag[b] = bk;
    }
}

// =====================================================================
// Backward: serial walk per batch through shared reloads + lengths.
// =====================================================================
__global__ __launch_bounds__(128) void bwd_kernel(const int* __restrict__ mask,
                                                  float* __restrict__ out) {
    const int b   = blockIdx.x;
    const int tid = threadIdx.x;

    __shared__ __align__(16) uint8_t wb[GRP][CHUNK][KK];   // 32 KB
    __shared__ __align__(16) float   tagseg[GRP * CHUNK];
    __shared__ int scur;

    if (tid == 0) scur = g_lasttag[b];

    const uint8_t* bpb = g_bp + (size_t)b * TT * KK;
    for (int base = NCH - GRP; base >= 0; base -= GRP) {
        const uint4* src = (const uint4*)(bpb + (size_t)base * CHUNK * KK);
        uint4* dst = (uint4*)wb;
#pragma unroll
        for (int i = 0; i < (GRP * CHUNK * KK / 16) / 128; ++i)
            dst[tid + 128 * i] = src[tid + 128 * i];
        __syncthreads();

        if (tid == 0) {
            int cur = scur;                 // tag at t = 64*(base+GRP) - 1
            for (int g = GRP - 1; g >= 0; --g) {
                tagseg[g * CHUNK + CHUNK - 1] = (float)cur;
                for (int r = CHUNK - 1; r >= 1; --r) {
                    cur = wb[g][r][cur];
                    tagseg[g * CHUNK + r - 1] = (float)cur;
                }
                cur = wb[g][0][cur];        // cross chunk boundary
            }
            scur = cur;
        }
        __syncthreads();

        float* ob = out + (size_t)b * TT + base * CHUNK;
#pragma unroll
        for (int i = 0; i < (GRP * CHUNK) / 128; ++i)
            ob[tid + 128 * i] = tagseg[tid + 128 * i];
        __syncthreads();
    }

    // sequence length
    {
        int s = 0;
        const int4* m = (const int4*)(mask + (size_t)b * TT);
        for (int i = tid; i < TT / 4; i += 128) {
            int4 v = m[i];
            s += v.x + v.y + v.z + v.w;
        }
#pragma unroll
        for (int off = 16; off; off >>= 1) s += __shfl_xor_sync(0xffffffffu, s, off);
        __shared__ int red[4];
        if ((tid & 31) == 0) red[tid >> 5] = s;
        __syncthreads();
        if (tid == 0)
            out[(size_t)BB * TT + b] = (float)(red[0] + red[1] + red[2] + red[3]);
    }
}

// =====================================================================
extern "C" void kernel_launch(void* const* d_in, const int* in_sizes, int n_in,
                              void* d_out, int out_size) {
    const float* pot   = nullptr;
    const float* trans = nullptr;
    const int*   mask  = nullptr;
    for (int i = 0; i < n_in; ++i) {
        if      (in_sizes[i] == BB * TT * KK) pot   = (const float*)d_in[i];
        else if (in_sizes[i] == KK * KK)      trans = (const float*)d_in[i];
        else if (in_sizes[i] == BB * TT)      mask  = (const int*)  d_in[i];
    }
    float* out = (float*)d_out;   // [tags (128*4096) | lengths (128)] as f32

    fwd_kernel<<<BB, 128>>>(pot, trans);
    bwd_kernel<<<BB, 128>>>(mask, out);
}

// round 11
// speedup vs baseline: 1.3640x; 1.2003x over previous
#include <cuda_runtime.h>
#include <cstdint>

#define BB 128
#define TT 4096
#define KK 64
#define CHUNK 64
#define NCH   (TT / CHUNK)   /* 64 chunks */
#define GRP   8              /* chunks per backward group (32 KB) */

// scratch (static __device__: allocation-free)
__device__ __align__(16) uint8_t g_bp[(size_t)BB * TT * KK];   // 32 MB backpointers
__device__ int g_lasttag[BB];

// dynamic smem layout
struct Smem {
    float   ebuf[2][CHUNK * KK];         // 32 KB emission double buffer
    float   aslab[2][(CHUNK + 1) * KK];  // 33.3 KB alpha rows (row 0 = alpha before chunk)
    float   bslab[2][CHUNK * KK];        // 32 KB per-step pre-emission max
    uint8_t bps[2][CHUNK * KK];          // 8 KB bp staging
};

__device__ __forceinline__ void cpasync16(uint32_t saddr, const void* gptr) {
    asm volatile("cp.async.ca.shared.global [%0], [%1], 16;" :: "r"(saddr), "l"(gptr));
}
__device__ __forceinline__ void cpasync_commit() { asm volatile("cp.async.commit_group;"); }
__device__ __forceinline__ void cpasync_wait1()  { asm volatile("cp.async.wait_group 1;"); }

__device__ __forceinline__ unsigned long long addx2(unsigned long long a, unsigned long long b) {
    unsigned long long d;
    asm("add.rn.f32x2 %0, %1, %2;" : "=l"(d) : "l"(a), "l"(b));
    return d;
}
__device__ __forceinline__ unsigned long long fma2(unsigned long long a, unsigned long long b,
                                                   unsigned long long c) {
    unsigned long long d;
    asm("fma.rn.f32x2 %0, %1, %2, %3;" : "=l"(d) : "l"(a), "l"(b), "l"(c));
    return d;
}
__device__ __forceinline__ float lo32(unsigned long long x) { return __uint_as_float((unsigned)x); }
__device__ __forceinline__ float hi32(unsigned long long x) { return __uint_as_float((unsigned)(x >> 32)); }
__device__ __forceinline__ unsigned long long pk2(float a, float b) {
    return (unsigned long long)__float_as_uint(a) | ((unsigned long long)__float_as_uint(b) << 32);
}

#define NEG1X2 0xBF800000BF800000ULL   /* (-1, -1) */
#define BIGX2  0x5F0000005F000000ULL   /* (2^63, 2^63) */

// =====================================================================
// Warp-specialized forward: warps 0-3 = VALUE (serial max recursion),
// warps 4-11 = BP (lag one chunk; recompute argmax via float keys).
// Exact: v recomputed bitwise-identically; d = RN(best - v) == +0 iff
// v == best; key = RN(d*2^63 + j) == j exactly for winners, > 63 for
// losers; min-key = first-index argmax (matches jnp.argmax).
// =====================================================================
__global__ void __launch_bounds__(384, 1) fwd_kernel(const float* __restrict__ pot,
                                                     const float* __restrict__ trans) {
    extern __shared__ char smraw[];
    Smem* sm = (Smem*)smraw;

    const int b    = blockIdx.x;
    const int tid  = threadIdx.x;
    const bool isVal = (tid < 128);
    const int stid  = isVal ? tid : ((tid - 128) & 127);
    const int slice = isVal ? 0 : ((tid - 128) >> 7);   // bp slice 0/1
    const int k  = stid >> 1;   // 0..63
    const int jh = stid & 1;    // 0..1

    // transition pairs (same layout for both groups)
    unsigned long long trp[16];
#pragma unroll
    for (int i = 0; i < 16; ++i)
        trp[i] = pk2(trans[(jh * 32 + 2 * i) * KK + k],
                     trans[(jh * 32 + 2 * i + 1) * KK + k]);

    unsigned long long idxp[16];
    if (!isVal) {
#pragma unroll
        for (int i = 0; i < 16; ++i)
            idxp[i] = pk2((float)(jh * 32 + 2 * i), (float)(jh * 32 + 2 * i + 1));
    }

    const float* pbm = pot + (size_t)b * TT * KK;

    if (isVal) {   // prologue: prefetch emission chunks 0, 1
        uint32_t s0 = (uint32_t)__cvta_generic_to_shared(sm->ebuf[0]);
        uint32_t s1 = (uint32_t)__cvta_generic_to_shared(sm->ebuf[1]);
#pragma unroll
        for (int i = 0; i < 8; ++i)
            cpasync16(s0 + (i * 128 + tid) * 16, pbm + (i * 128 + tid) * 4);
        cpasync_commit();
#pragma unroll
        for (int i = 0; i < 8; ++i)
            cpasync16(s1 + (i * 128 + tid) * 16, pbm + CHUNK * KK + (i * 128 + tid) * 4);
        cpasync_commit();
        cpasync_wait1();
    }
    __syncthreads();
    if (isVal && jh == 0)
        sm->aslab[0][KK + k] = sm->ebuf[0][k];   // alpha_0 -> chunk0 row 1

    for (int p = 0; p <= NCH; ++p) {
        const int pb = p & 1;

        if (isVal && p < NCH) {
            if (p > 0 && jh == 0)   // carry alpha_{p*64-1} into row 0
                sm->aslab[pb][k] = sm->aslab[pb ^ 1][CHUNK * KK + k];
            asm volatile("bar.sync 1, 128;" ::: "memory");

            const float* eb = sm->ebuf[pb];
            const int r0 = (p == 0) ? 1 : 0;
            for (int r = r0; r < CHUNK; ++r) {
                const float* srow = sm->aslab[pb] + r * KK + jh * 32;
                float emit = eb[r * KK + k];

                unsigned long long vp[16];
#pragma unroll
                for (int i = 0; i < 8; ++i) {
                    ulonglong2 sv = ((const ulonglong2*)srow)[i];
                    vp[2 * i]     = addx2(sv.x, trp[2 * i]);
                    vp[2 * i + 1] = addx2(sv.y, trp[2 * i + 1]);
                }
                float mx[16];
#pragma unroll
                for (int i = 0; i < 16; ++i) mx[i] = fmaxf(lo32(vp[i]), hi32(vp[i]));
#pragma unroll
                for (int i = 0; i < 8; ++i)  mx[i] = fmaxf(mx[2 * i], mx[2 * i + 1]);
#pragma unroll
                for (int i = 0; i < 4; ++i)  mx[i] = fmaxf(mx[2 * i], mx[2 * i + 1]);
                float vmax = fmaxf(fmaxf(mx[0], mx[1]), fmaxf(mx[2], mx[3]));

                float po   = __shfl_xor_sync(0xffffffffu, vmax, 1);
                float best = fmaxf(vmax, po);

                if (jh == 0) {
                    sm->bslab[pb][r * KK + k]       = best;
                    sm->aslab[pb][(r + 1) * KK + k] = best + emit;
                }
                asm volatile("bar.sync 1, 128;" ::: "memory");
            }

            if (p == NCH - 1 && tid == 0) {   // last tag from final alpha row
                const float* fin = sm->aslab[pb] + CHUNK * KK;
                float bv = fin[0]; int bk = 0;
#pragma unroll
                for (int kk = 1; kk < KK; ++kk) {
                    float vv = fin[kk];
                    if (vv > bv) { bv = vv; bk = kk; }
                }
                g_lasttag[b] = bk;
            }

            if (p + 1 < NCH) {   // prefetch chunk p+2 into freed ebuf[pb]
                if (p + 2 < NCH) {
                    uint32_t sn = (uint32_t)__cvta_generic_to_shared(sm->ebuf[pb]);
                    const float* gsrc = pbm + (size_t)(p + 2) * CHUNK * KK;
#pragma unroll
                    for (int i = 0; i < 8; ++i)
                        cpasync16(sn + (i * 128 + tid) * 16, gsrc + (i * 128 + tid) * 4);
                }
                cpasync_commit();
                cpasync_wait1();   // chunk p+1 resident
            }
        }

        if (!isVal && p >= 1) {   // bp for chunk q = p-1 (slabs stable this phase)
            const int q  = p - 1;
            const int qb = q & 1;
            const int rbase = slice * 32;
#pragma unroll 2
            for (int rr = 0; rr < 32; ++rr) {
                const int r = rbase + rr;
                if (q == 0 && r == 0) {
                    if (jh == 0) sm->bps[qb][k] = (uint8_t)k;   // never applied
                    continue;
                }
                const float* arow = sm->aslab[qb] + r * KK + jh * 32;
                float bestv = sm->bslab[qb][r * KK + k];
                unsigned long long bestp = pk2(bestv, bestv);

                unsigned long long vp[16];
#pragma unroll
                for (int i = 0; i < 8; ++i) {
                    ulonglong2 sv = ((const ulonglong2*)arow)[i];
                    vp[2 * i]     = addx2(sv.x, trp[2 * i]);
                    vp[2 * i + 1] = addx2(sv.y, trp[2 * i + 1]);
                }
                float kf[16];
#pragma unroll
                for (int i = 0; i < 16; ++i) {
                    unsigned long long dp = fma2(vp[i], NEG1X2, bestp); // best - v >= +0
                    unsigned long long kp = fma2(dp, BIGX2, idxp[i]);   // j exact if d==0
                    kf[i] = fminf(lo32(kp), hi32(kp));
                }
#pragma unroll
                for (int i = 0; i < 8; ++i) kf[i] = fminf(kf[2 * i], kf[2 * i + 1]);
#pragma unroll
                for (int i = 0; i < 4; ++i) kf[i] = fminf(kf[2 * i], kf[2 * i + 1]);
                float kmin = fminf(fminf(kf[0], kf[1]), fminf(kf[2], kf[3]));
                float pk   = __shfl_xor_sync(0xffffffffu, kmin, 1);
                kmin = fminf(kmin, pk);

                if (jh == 0) sm->bps[qb][r * KK + k] = (uint8_t)(int)kmin;
            }
            // slice-local sync, then flush own 2 KB of bps to global
            asm volatile("bar.sync %0, 128;" :: "r"(2 + slice) : "memory");
            {
                uint4*       dst = (uint4*)(g_bp + (size_t)b * TT * KK + (size_t)q * CHUNK * KK);
                const uint4* src = (const uint4*)sm->bps[qb];
                const int off = slice * 128 + stid;
                dst[off] = src[off];
            }
        }
        __syncthreads();   // chunk handoff
    }
}

// =====================================================================
// Backward: serial walk per batch through shared reloads + lengths.
// =====================================================================
__global__ __launch_bounds__(128) void bwd_kernel(const int* __restrict__ mask,
                                                  float* __restrict__ out) {
    const int b   = blockIdx.x;
    const int tid = threadIdx.x;

    __shared__ __align__(16) uint8_t wb[GRP][CHUNK][KK];   // 32 KB
    __shared__ __align__(16) float   tagseg[GRP * CHUNK];
    __shared__ int scur;

    if (tid == 0) scur = g_lasttag[b];

    const uint8_t* bpb = g_bp + (size_t)b * TT * KK;
    for (int base = NCH - GRP; base >= 0; base -= GRP) {
        const uint4* src = (const uint4*)(bpb + (size_t)base * CHUNK * KK);
        uint4* dst = (uint4*)wb;
#pragma unroll
        for (int i = 0; i < (GRP * CHUNK * KK / 16) / 128; ++i)
            dst[tid + 128 * i] = src[tid + 128 * i];
        __syncthreads();

        if (tid == 0) {
            int cur = scur;                 // tag at t = 64*(base+GRP) - 1
            for (int g = GRP - 1; g >= 0; --g) {
                tagseg[g * CHUNK + CHUNK - 1] = (float)cur;
                for (int r = CHUNK - 1; r >= 1; --r) {
                    cur = wb[g][r][cur];
                    tagseg[g * CHUNK + r - 1] = (float)cur;
                }
                cur = wb[g][0][cur];        // cross chunk boundary
            }
            scur = cur;
        }
        __syncthreads();

        float* ob = out + (size_t)b * TT + base * CHUNK;
#pragma unroll
        for (int i = 0; i < (GRP * CHUNK) / 128; ++i)
            ob[tid + 128 * i] = tagseg[tid + 128 * i];
        __syncthreads();
    }

    // sequence length
    {
        int s = 0;
        const int4* m = (const int4*)(mask + (size_t)b * TT);
        for (int i = tid; i < TT / 4; i += 128) {
            int4 v = m[i];
            s += v.x + v.y + v.z + v.w;
        }
#pragma unroll
        for (int off = 16; off; off >>= 1) s += __shfl_xor_sync(0xffffffffu, s, off);
        __shared__ int red[4];
        if ((tid & 31) == 0) red[tid >> 5] = s;
        __syncthreads();
        if (tid == 0)
            out[(size_t)BB * TT + b] = (float)(red[0] + red[1] + red[2] + red[3]);
    }
}

// =====================================================================
extern "C" void kernel_launch(void* const* d_in, const int* in_sizes, int n_in,
                              void* d_out, int out_size) {
    const float* pot   = nullptr;
    const float* trans = nullptr;
    const int*   mask  = nullptr;
    for (int i = 0; i < n_in; ++i) {
        if      (in_sizes[i] == BB * TT * KK) pot   = (const float*)d_in[i];
        else if (in_sizes[i] == KK * KK)      trans = (const float*)d_in[i];
        else if (in_sizes[i] == BB * TT)      mask  = (const int*)  d_in[i];
    }
    float* out = (float*)d_out;   // [tags (128*4096) | lengths (128)] as f32

    cudaFuncSetAttribute(fwd_kernel, cudaFuncAttributeMaxDynamicSharedMemorySize,
                         (int)sizeof(Smem));
    fwd_kernel<<<BB, 384, sizeof(Smem)>>>(pot, trans);
    bwd_kernel<<<BB, 128>>>(mask, out);
}